// round 9
// baseline (speedup 1.0000x reference)
#include <cuda_runtime.h>

// Lifting wavelet v9: shuffle-halo streaming. 8 pairs/thread, each thread loads
// ONLY its own 16 floats (read amplification 1.0x); the 16-float left halo
// comes from lane-1 via __shfl_up_sync (lane 0 loads it globally). Taps in
// __constant__ (LDC, no pinned regs) written by a tiny setup kernel.
// input: (4096, 8192) f32. even = in[:, ::2], odd = in[:, 1::2] (4096 each).
// wavelet[j] = scaling_rec[7-j] * (j odd ? -1 : +1)
// odd_out[k]  = odd[k]  - sum_j wavelet[j] * even[(k-j) mod 4096]
// even_out[k] = even[k] - sum_j scaling[j] * odd[(k-j) mod 4096]
// Output: [even_updated | odd_updated], each 4096x4096 f32.

#define ROWS    4096
#define ROWLEN  8192
#define HALF    4096
#define NTH     256
#define FMASK   (ROWLEN - 1)

// [0..7] wavelet (reversed+sign-flipped), [8..15] scaling.
__constant__ float cTaps[16];

__global__ void wavelet_setup(const float* __restrict__ scaling,
                              const float* __restrict__ scaling_rec,
                              float* __restrict__ taps_dst)
{
    int t = threadIdx.x;
    if (t < 8) {
        float w = scaling_rec[7 - t];
        taps_dst[t]     = (t & 1) ? -w : w;
        taps_dst[8 + t] = scaling[t];
    }
}

__global__ __launch_bounds__(NTH, 4)   // cap 64 regs: window must not spill
void wavelet_fwd_v9(const float* __restrict__ in,
                    float* __restrict__ out)
{
    const int g    = blockIdx.x * NTH + threadIdx.x;  // 0 .. 2M-1
    const int row  = g >> 9;                           // 512 threads per row
    const int lk   = (g & 511) << 3;                   // pair base: 0..4088
    const int lane = threadIdx.x & 31;

    const float* rowp = in + (size_t)row * ROWLEN;

    // Own 16 floats: row[2lk .. 2lk+15]  (4 LDG.128, amplification 1.0x).
    float f[16];
    {
        const float4* p = reinterpret_cast<const float4*>(rowp + 2 * lk);
#pragma unroll
        for (int q = 0; q < 4; q++) {
            float4 v = p[q];
            f[4*q+0] = v.x; f[4*q+1] = v.y; f[4*q+2] = v.z; f[4*q+3] = v.w;
        }
    }

    // Lane 0 of each warp: left halo row[(2lk-16 .. 2lk-1) mod 8192] from global.
    // (Consecutive lanes own consecutive 8-pair segments; blocks never span rows.)
    float h[16];
    if (lane == 0) {
#pragma unroll
        for (int q = 0; q < 4; q++) {
            int fi = (2 * lk - 16 + 4 * q) & FMASK;
            float4 v = *reinterpret_cast<const float4*>(rowp + fi);
            h[4*q+0] = v.x; h[4*q+1] = v.y; h[4*q+2] = v.z; h[4*q+3] = v.w;
        }
    }

    // Window wnd[0..31] = row[2lk-16 .. 2lk+15]:
    //   wnd[j]    (j<16) = lane-1's f[j]  (shfl), lane 0 uses global halo h[j]
    //   wnd[16+j]        = own f[j]
    float wnd[32];
#pragma unroll
    for (int j = 0; j < 16; j++) {
        float s = __shfl_up_sync(0xffffffffu, f[j], 1);
        wnd[j]      = (lane == 0) ? h[j] : s;
        wnd[16 + j] = f[j];
    }

    // Taps via LDC (rematerializable, no pinned registers).
    const float w0 = cTaps[0], w1 = cTaps[1], w2 = cTaps[2], w3 = cTaps[3];
    const float w4 = cTaps[4], w5 = cTaps[5], w6 = cTaps[6], w7 = cTaps[7];
    const float c0 = cTaps[8],  c1 = cTaps[9],  c2 = cTaps[10], c3 = cTaps[11];
    const float c4 = cTaps[12], c5 = cTaps[13], c6 = cTaps[14], c7 = cTaps[15];

    const size_t obase = (size_t)row * HALF + lk;
    float4* pe = reinterpret_cast<float4*>(out + obase);
    float4* po = reinterpret_cast<float4*>(out + (size_t)ROWS * HALF + obase);

    // Two 4-pair phases to cap live accumulators at 8.
#pragma unroll
    for (int half = 0; half < 2; half++) {
        float rE[4], rO[4];
#pragma unroll
        for (int m4 = 0; m4 < 4; m4++) {
            const int m = 4 * half + m4;
            const int b = 2 * m + 16;          // even of pair (lk+m)
            float e8 = wnd[b], o8 = wnd[b + 1];
            float ce = w0*e8
                     + w1*wnd[b-2]  + w2*wnd[b-4]  + w3*wnd[b-6]
                     + w4*wnd[b-8]  + w5*wnd[b-10] + w6*wnd[b-12]
                     + w7*wnd[b-14];
            float co = c0*o8
                     + c1*wnd[b-1]  + c2*wnd[b-3]  + c3*wnd[b-5]
                     + c4*wnd[b-7]  + c5*wnd[b-9]  + c6*wnd[b-11]
                     + c7*wnd[b-13];
            rO[m4] = o8 - ce;   // odd  - conv(even, wavelet)
            rE[m4] = e8 - co;   // even - conv(odd,  scaling)
        }
        pe[half] = make_float4(rE[0], rE[1], rE[2], rE[3]);
        po[half] = make_float4(rO[0], rO[1], rO[2], rO[3]);
    }
}

extern "C" void kernel_launch(void* const* d_in, const int* in_sizes, int n_in,
                              void* d_out, int out_size)
{
    const float* input       = (const float*)d_in[0];
    const float* scaling     = (const float*)d_in[1];
    const float* scaling_rec = (const float*)d_in[2];
    float* out = (float*)d_out;

    float* taps_dst = nullptr;
    cudaGetSymbolAddress((void**)&taps_dst, cTaps);
    wavelet_setup<<<1, 32>>>(scaling, scaling_rec, taps_dst);

    const int total_threads = ROWS * (HALF / 8);       // 2M
    wavelet_fwd_v9<<<total_threads / NTH, NTH>>>(input, out);
}

// round 10
// speedup vs baseline: 1.0366x; 1.0366x over previous
#include <cuda_runtime.h>

// Lifting wavelet v10: shuffle-halo, 4 pairs/thread, LDC taps.
// Own segment: 8 floats (2x LDG.128, read amplification 1.0x).
// Halo (16 floats) from lanes -1/-2 via shfl_up; lanes 0..1 load their missing
// halo part straight into the window (no separate halo array -> no wasted regs).
// Taps in __constant__ written by a tiny setup kernel (LDC = rematerializable,
// keeps the window register-resident at high occupancy).
// input: (4096, 8192) f32. even = in[:, ::2], odd = in[:, 1::2] (4096 each).
// wavelet[j] = scaling_rec[7-j] * (j odd ? -1 : +1)
// odd_out[k]  = odd[k]  - sum_j wavelet[j] * even[(k-j) mod 4096]
// even_out[k] = even[k] - sum_j scaling[j] * odd[(k-j) mod 4096]
// Output: [even_updated | odd_updated], each 4096x4096 f32.

#define ROWS    4096
#define ROWLEN  8192
#define HALF    4096
#define NTH     256
#define FMASK   (ROWLEN - 1)

// [0..7] wavelet (reversed+sign-flipped), [8..15] scaling.
__constant__ float cTaps[16];

__global__ void wavelet_setup(const float* __restrict__ scaling,
                              const float* __restrict__ scaling_rec,
                              float* __restrict__ taps_dst)
{
    int t = threadIdx.x;
    if (t < 8) {
        float w = scaling_rec[7 - t];
        taps_dst[t]     = (t & 1) ? -w : w;
        taps_dst[8 + t] = scaling[t];
    }
}

__global__ __launch_bounds__(NTH, 6)   // <=42 regs; 24-float window must fit
void wavelet_fwd_v10(const float* __restrict__ in,
                     float* __restrict__ out)
{
    const int g    = blockIdx.x * NTH + threadIdx.x;  // 0 .. 4M-1
    const int row  = g >> 10;                          // 1024 threads per row
    const int lk   = (g & 1023) << 2;                  // pair base: 0..4092
    const int lane = threadIdx.x & 31;

    const float* rowp = in + (size_t)row * ROWLEN;

    // wnd[j] = row[(2lk-16+j) mod 8192], j = 0..23.
    float wnd[24];

    // Own 8 floats: row[2lk .. 2lk+7] -> wnd[16..23]. Amplification 1.0x.
    {
        const float4* p = reinterpret_cast<const float4*>(rowp + 2 * lk);
        float4 v0 = p[0];
        float4 v1 = p[1];
        wnd[16] = v0.x; wnd[17] = v0.y; wnd[18] = v0.z; wnd[19] = v0.w;
        wnd[20] = v1.x; wnd[21] = v1.y; wnd[22] = v1.z; wnd[23] = v1.w;
    }

    // Halo via shuffles (consecutive lanes own consecutive 4-pair segments;
    // blocks never span rows, so lane-1/lane-2 segments are the needed floats):
    //   lane-1 owns row[2lk-8 .. 2lk-1]  -> wnd[8..15]
    //   lane-2 owns row[2lk-16 .. 2lk-9] -> wnd[0..7]
#pragma unroll
    for (int i = 0; i < 8; i++) {
        wnd[8 + i] = __shfl_up_sync(0xffffffffu, wnd[16 + i], 1);
        wnd[i]     = __shfl_up_sync(0xffffffffu, wnd[16 + i], 2);
    }

    // Lanes 0,1 fix up the parts their shuffles couldn't provide, loading
    // straight into wnd (circular wrap handled by & FMASK).
    if (lane < 2) {
        // wnd[0..7] invalid for lanes 0 and 1.
#pragma unroll
        for (int q = 0; q < 2; q++) {
            int fi = (2 * lk - 16 + 4 * q) & FMASK;
            float4 v = *reinterpret_cast<const float4*>(rowp + fi);
            wnd[4*q+0] = v.x; wnd[4*q+1] = v.y; wnd[4*q+2] = v.z; wnd[4*q+3] = v.w;
        }
        if (lane == 0) {
            // wnd[8..15] invalid for lane 0 only.
#pragma unroll
            for (int q = 0; q < 2; q++) {
                int fi = (2 * lk - 8 + 4 * q) & FMASK;
                float4 v = *reinterpret_cast<const float4*>(rowp + fi);
                wnd[8+4*q+0] = v.x; wnd[8+4*q+1] = v.y;
                wnd[8+4*q+2] = v.z; wnd[8+4*q+3] = v.w;
            }
        }
    }

    // Taps via LDC (rematerializable, no pinned registers).
    const float w0 = cTaps[0], w1 = cTaps[1], w2 = cTaps[2], w3 = cTaps[3];
    const float w4 = cTaps[4], w5 = cTaps[5], w6 = cTaps[6], w7 = cTaps[7];
    const float c0 = cTaps[8],  c1 = cTaps[9],  c2 = cTaps[10], c3 = cTaps[11];
    const float c4 = cTaps[12], c5 = cTaps[13], c6 = cTaps[14], c7 = cTaps[15];

    // Pair (lk+m): even = wnd[2m+16], odd = wnd[2m+17].
    float rE[4], rO[4];
#pragma unroll
    for (int m = 0; m < 4; m++) {
        const int b = 2 * m + 16;
        float e8 = wnd[b], o8 = wnd[b + 1];
        float ce = w0*e8
                 + w1*wnd[b-2]  + w2*wnd[b-4]  + w3*wnd[b-6]
                 + w4*wnd[b-8]  + w5*wnd[b-10] + w6*wnd[b-12]
                 + w7*wnd[b-14];
        float co = c0*o8
                 + c1*wnd[b-1]  + c2*wnd[b-3]  + c3*wnd[b-5]
                 + c4*wnd[b-7]  + c5*wnd[b-9]  + c6*wnd[b-11]
                 + c7*wnd[b-13];
        rO[m] = o8 - ce;   // odd  - conv(even, wavelet)
        rE[m] = e8 - co;   // even - conv(odd,  scaling)
    }

    const size_t obase = (size_t)row * HALF + lk;
    *reinterpret_cast<float4*>(out + obase) =
        make_float4(rE[0], rE[1], rE[2], rE[3]);
    *reinterpret_cast<float4*>(out + (size_t)ROWS * HALF + obase) =
        make_float4(rO[0], rO[1], rO[2], rO[3]);
}

extern "C" void kernel_launch(void* const* d_in, const int* in_sizes, int n_in,
                              void* d_out, int out_size)
{
    const float* input       = (const float*)d_in[0];
    const float* scaling     = (const float*)d_in[1];
    const float* scaling_rec = (const float*)d_in[2];
    float* out = (float*)d_out;

    float* taps_dst = nullptr;
    cudaGetSymbolAddress((void**)&taps_dst, cTaps);
    wavelet_setup<<<1, 32>>>(scaling, scaling_rec, taps_dst);

    const int total_threads = ROWS * (HALF / 4);       // 4M
    wavelet_fwd_v10<<<total_threads / NTH, NTH>>>(input, out);
}